// round 13
// baseline (speedup 1.0000x reference)
#include <cuda_runtime.h>
#include <cuda_bf16.h>

// out[n,:] = x[n,:] * min(1, 1/||x[n,:]||) + noise[n,:]   (L2_NORM_CLIP = 1)
// N = 524288 rows, D = 128 fp32.
//
// One warp per row-slot, grid-stride over 4 rows per warp with a 1-deep
// software pipeline: the NEXT row's x/noise loads are issued before the
// current row's shfl reduction + store, keeping 2 LDG.128 per thread in
// flight continuously (no dead window during the ~150-cycle reduction chain).
// All traffic is zero-reuse, so use .cs (evict-first streaming) on both
// loads and the store.

__global__ __launch_bounds__(256) void dp_clip_noise_kernel(
    const float4* __restrict__ x,
    const float4* __restrict__ noise,
    float4* __restrict__ out,
    int nrows)
{
    const int lane   = threadIdx.x & 31;
    const int warp   = (int)((blockIdx.x * blockDim.x + threadIdx.x) >> 5);
    const int nwarps = (int)((gridDim.x * blockDim.x) >> 5);

    int row = warp;
    if (row >= nrows) return;

    long long idx = (long long)row * 32 + lane;
    float4 xv = __ldcs(x + idx);
    float4 nv = __ldcs(noise + idx);

    while (true) {
        // ---- prefetch next row (issued before the reduction chain) ----
        const int next = row + nwarps;
        const bool more = next < nrows;
        float4 xn, nn;
        long long nidx = 0;
        if (more) {
            nidx = (long long)next * 32 + lane;
            xn = __ldcs(x + nidx);
            nn = __ldcs(noise + nidx);
        }

        // ---- process current row ----
        float ssq = xv.x * xv.x + xv.y * xv.y + xv.z * xv.z + xv.w * xv.w;
        #pragma unroll
        for (int off = 16; off > 0; off >>= 1)
            ssq += __shfl_xor_sync(0xFFFFFFFFu, ssq, off);

        // scale = 1/max(norm,1) = min(1, rsqrt(ssq)); ssq==0 -> inf -> 1.
        const float scale = fminf(1.0f, rsqrtf(ssq));

        float4 ov;
        ov.x = fmaf(xv.x, scale, nv.x);
        ov.y = fmaf(xv.y, scale, nv.y);
        ov.z = fmaf(xv.z, scale, nv.z);
        ov.w = fmaf(xv.w, scale, nv.w);
        __stcs(out + idx, ov);

        if (!more) break;
        row = next;
        idx = nidx;
        xv  = xn;
        nv  = nn;
    }
}

extern "C" void kernel_launch(void* const* d_in, const int* in_sizes, int n_in,
                              void* d_out, int out_size)
{
    const float4* x     = (const float4*)d_in[0];
    const float4* noise = (const float4*)d_in[1];
    float4* out         = (float4*)d_out;

    const int D = 128;
    const int nrows = in_sizes[0] / D;          // 524288

    // 8 warps per CTA, 4 rows per warp -> 16384 CTAs (vs 65536 before):
    // fewer wave transitions, and the pipeline keeps loads in flight.
    const int threads = 256;
    const int rows_per_warp = 4;
    const int warps_per_block = threads / 32;
    int blocks = (nrows + warps_per_block * rows_per_warp - 1)
               / (warps_per_block * rows_per_warp);
    if (blocks < 1) blocks = 1;

    dp_clip_noise_kernel<<<blocks, threads>>>(x, noise, out, nrows);
}

// round 14
// speedup vs baseline: 1.0077x; 1.0077x over previous
#include <cuda_runtime.h>
#include <cuda_bf16.h>

// out[n,:] = x[n,:] * min(1, 1/||x[n,:]||) + noise[n,:]   (L2_NORM_CLIP = 1)
// N = 524288 rows, D = 128 fp32.
//
// One warp per ROW-PAIR: lane i loads float4 chunk i of row 2p and of row
// 2p+1 (warp covers 1024 contiguous bytes per tensor, fully coalesced).
// Per iteration: 4 front-batched LDG.128 per thread + 4 prefetched for the
// next pair (up to 8 in flight), then TWO independent shfl reduction chains
// interleaved (ILP=2 hides the cross-lane latency), then 2 STG.128.
// All traffic is zero-reuse -> .cs streaming hints everywhere.

__global__ __launch_bounds__(256) void dp_clip_noise_kernel(
    const float4* __restrict__ x,
    const float4* __restrict__ noise,
    float4* __restrict__ out,
    int nrows)
{
    const int lane   = threadIdx.x & 31;
    const int warp   = (int)((blockIdx.x * blockDim.x + threadIdx.x) >> 5);
    const int nwarps = (int)((gridDim.x * blockDim.x) >> 5);

    const int npairs = nrows >> 1;              // rows are processed in pairs
    int pair = warp;
    if (pair >= npairs) return;

    // Pair p covers float4 indices [p*64, p*64+64): row 2p at +lane,
    // row 2p+1 at +32+lane.
    long long idx = (long long)pair * 64 + lane;
    float4 xv0 = __ldcs(x + idx);
    float4 nv0 = __ldcs(noise + idx);
    float4 xv1 = __ldcs(x + idx + 32);
    float4 nv1 = __ldcs(noise + idx + 32);

    while (true) {
        // ---- prefetch next pair (issued before the reduction chains) ----
        const int next = pair + nwarps;
        const bool more = next < npairs;
        float4 xp0, np0, xp1, np1;
        long long nidx = 0;
        if (more) {
            nidx = (long long)next * 64 + lane;
            xp0 = __ldcs(x + nidx);
            np0 = __ldcs(noise + nidx);
            xp1 = __ldcs(x + nidx + 32);
            np1 = __ldcs(noise + nidx + 32);
        }

        // ---- two independent reductions, interleaved for ILP ----
        float s0 = xv0.x * xv0.x + xv0.y * xv0.y + xv0.z * xv0.z + xv0.w * xv0.w;
        float s1 = xv1.x * xv1.x + xv1.y * xv1.y + xv1.z * xv1.z + xv1.w * xv1.w;
        #pragma unroll
        for (int off = 16; off > 0; off >>= 1) {
            s0 += __shfl_xor_sync(0xFFFFFFFFu, s0, off);
            s1 += __shfl_xor_sync(0xFFFFFFFFu, s1, off);
        }

        // scale = 1/max(norm,1) = min(1, rsqrt(ssq)); ssq==0 -> inf -> 1.
        const float sc0 = fminf(1.0f, rsqrtf(s0));
        const float sc1 = fminf(1.0f, rsqrtf(s1));

        float4 o0, o1;
        o0.x = fmaf(xv0.x, sc0, nv0.x);
        o0.y = fmaf(xv0.y, sc0, nv0.y);
        o0.z = fmaf(xv0.z, sc0, nv0.z);
        o0.w = fmaf(xv0.w, sc0, nv0.w);
        o1.x = fmaf(xv1.x, sc1, nv1.x);
        o1.y = fmaf(xv1.y, sc1, nv1.y);
        o1.z = fmaf(xv1.z, sc1, nv1.z);
        o1.w = fmaf(xv1.w, sc1, nv1.w);
        __stcs(out + idx,      o0);
        __stcs(out + idx + 32, o1);

        if (!more) break;
        pair = next;
        idx  = nidx;
        xv0 = xp0; nv0 = np0;
        xv1 = xp1; nv1 = np1;
    }
}

extern "C" void kernel_launch(void* const* d_in, const int* in_sizes, int n_in,
                              void* d_out, int out_size)
{
    const float4* x     = (const float4*)d_in[0];
    const float4* noise = (const float4*)d_in[1];
    float4* out         = (float4*)d_out;

    const int D = 128;
    const int nrows = in_sizes[0] / D;          // 524288
    const int npairs = nrows / 2;               // 262144

    // 8 warps per CTA, 2 pairs (4 rows) per warp -> 16384 CTAs.
    const int threads = 256;
    const int pairs_per_warp = 2;
    const int warps_per_block = threads / 32;
    int blocks = (npairs + warps_per_block * pairs_per_warp - 1)
               / (warps_per_block * pairs_per_warp);
    if (blocks < 1) blocks = 1;

    dp_clip_noise_kernel<<<blocks, threads>>>(x, noise, out, nrows);
}